// round 8
// baseline (speedup 1.0000x reference)
#include <cuda_runtime.h>
#include <cuda_fp16.h>
#include <cuda_fp8.h>
#include <cstdint>

#define DEV_INLINE __device__ __forceinline__

// ---------------------------------------------------------------------------
// Scratch (static device globals — allocation-free per harness rules)
// M=16384, K=4096, N=4096.
// ---------------------------------------------------------------------------
static __device__ __half g_A[(size_t)16384 * 4096];  // dequant x, fp16, [M,K]
static __device__ __half g_B[(size_t)4096 * 4096];   // dequant W, fp16, [K,N]

// ---------------------------------------------------------------------------
// Quantize + dequantize (DRAM-bound; exact reference math).
// scale = max(amax/448, 1e-12); q = fp8_e4m3(v/scale); dq = float(q)*scale;
// one fp16 rounding at the end (only added approximation).
// ---------------------------------------------------------------------------
__global__ void quant_kernel(const float* __restrict__ in,
                             __half* __restrict__ out, int nquads) {
    const int quad = (blockIdx.x * blockDim.x + threadIdx.x) >> 5;
    const int lane = threadIdx.x & 31;
    if (quad >= nquads) return;
    const size_t base = (size_t)quad * 512;

    float4 v[4];
#pragma unroll
    for (int b = 0; b < 4; b++)
        v[b] = reinterpret_cast<const float4*>(in + base + b * 128)[lane];

    float am[4];
#pragma unroll
    for (int b = 0; b < 4; b++)
        am[b] = fmaxf(fmaxf(fabsf(v[b].x), fabsf(v[b].y)),
                      fmaxf(fabsf(v[b].z), fabsf(v[b].w)));
#pragma unroll
    for (int o = 16; o > 0; o >>= 1) {
#pragma unroll
        for (int b = 0; b < 4; b++)
            am[b] = fmaxf(am[b], __shfl_xor_sync(0xFFFFFFFFu, am[b], o));
    }

#pragma unroll
    for (int b = 0; b < 4; b++) {
        const float s = fmaxf(__fdiv_rn(am[b], 448.0f), 1e-12f);
        float f[4] = {v[b].x, v[b].y, v[b].z, v[b].w};
        __half h[4];
#pragma unroll
        for (int i = 0; i < 4; i++) {
            __nv_fp8_storage_t q =
                __nv_cvt_float_to_fp8(__fdiv_rn(f[i], s), __NV_SATFINITE, __NV_E4M3);
            __half_raw hr = __nv_cvt_fp8_to_halfraw(q, __NV_E4M3);
            h[i] = __float2half_rn(__half2float(__half(hr)) * s);
        }
        reinterpret_cast<uint2*>(out + base + b * 128)[lane] =
            *reinterpret_cast<const uint2*>(h);
    }
}

// ---------------------------------------------------------------------------
// Persistent mma.sync GEMM: C = A @ B + bias.
// 296 CTAs (2/SM), each walks tiles bid, bid+296, ... as ONE linearized
// stream of (tile, kt) stages: the cp.async pipeline never drains across
// tile boundaries; epilogue (register->gmem) overlaps next tile's loads.
// CTA tile 128x128x64, 3 stages, 8 warps (2Mx4N), warp tile 64x32.
// ---------------------------------------------------------------------------
static constexpr int BM = 128, BN = 128, BK = 64, STAGES = 3;
static constexpr int LDA = BK + 8;    // 72 halves (conflict-free ldsm)
static constexpr int LDB = BN + 8;    // 136 halves
static constexpr int A_STAGE = BM * LDA;
static constexpr int B_STAGE = BK * LDB;
static constexpr size_t SMEM_BYTES = (size_t)STAGES * (A_STAGE + B_STAGE) * 2;  // 107520
static constexpr int NCTA = 296;      // 148 SMs x 2

DEV_INLINE uint32_t smem_u32(const void* p) {
    return (uint32_t)__cvta_generic_to_shared(p);
}
DEV_INLINE void cp_async_16(uint32_t dst, const void* src) {
    asm volatile("cp.async.cg.shared.global [%0], [%1], 16;\n" :: "r"(dst), "l"(src));
}
DEV_INLINE void cp_commit() { asm volatile("cp.async.commit_group;\n"); }
template <int NN> DEV_INLINE void cp_wait() {
    asm volatile("cp.async.wait_group %0;\n" :: "n"(NN));
}
DEV_INLINE void ldsm_x4(uint32_t* r, uint32_t addr) {
    asm volatile("ldmatrix.sync.aligned.m8n8.x4.shared.b16 {%0,%1,%2,%3}, [%4];"
                 : "=r"(r[0]), "=r"(r[1]), "=r"(r[2]), "=r"(r[3]) : "r"(addr));
}
DEV_INLINE void ldsm_x4_t(uint32_t* r, uint32_t addr) {
    asm volatile("ldmatrix.sync.aligned.m8n8.x4.trans.shared.b16 {%0,%1,%2,%3}, [%4];"
                 : "=r"(r[0]), "=r"(r[1]), "=r"(r[2]), "=r"(r[3]) : "r"(addr));
}
DEV_INLINE void mma_16816(float* d, const uint32_t* a, const uint32_t* b) {
    asm volatile(
        "mma.sync.aligned.m16n8k16.row.col.f32.f16.f16.f32 "
        "{%0,%1,%2,%3}, {%4,%5,%6,%7}, {%8,%9}, {%0,%1,%2,%3};"
        : "+f"(d[0]), "+f"(d[1]), "+f"(d[2]), "+f"(d[3])
        : "r"(a[0]), "r"(a[1]), "r"(a[2]), "r"(a[3]), "r"(b[0]), "r"(b[1]));
}

// panel-swizzled tile id -> (bm, bn): panels of 16 bm x 32 bn
DEV_INLINE void tile_coords(int t, int& bm, int& bn) {
    bm = (t >> 9) * 16 + (t & 15);
    bn = (t >> 4) & 31;
}

__global__ void __launch_bounds__(256, 2)
gemm_mma_persist(const __half* __restrict__ A, const __half* __restrict__ B,
                 const float* __restrict__ bias, float* __restrict__ C,
                 int M, int N, int K, int nTilesTotal) {
    extern __shared__ __align__(128) __half smem[];
    __half* sA = smem;                          // [STAGES][BM][LDA]
    __half* sB = smem + STAGES * A_STAGE;       // [STAGES][BK][LDB]

    const int tid = threadIdx.x;
    const int lane = tid & 31;
    const int warp = tid >> 5;
    const int wm = (warp & 1) * 64;
    const int wn = (warp >> 1) * 32;

    const uint32_t sAu = smem_u32(sA);
    const uint32_t sBu = smem_u32(sB);
    const int KT = K / BK;                      // 64
    const int bid = blockIdx.x;
    const int nMyTiles = (nTilesTotal - bid + NCTA - 1) / NCTA;
    if (nMyTiles <= 0) return;
    const int totalStages = nMyTiles * KT;

    // issue stage buffer `buf` <- linear stage ls (this CTA's stream)
    auto issue = [&](int buf, int ls) {
        const int ti = ls >> 6;                 // KT = 64
        const int kt = ls & 63;
        int bm, bn;
        tile_coords(bid + ti * NCTA, bm, bn);
        const __half* Ab = A + (size_t)bm * BM * K;
        const __half* Bb = B + (size_t)bn * BN;
        const int k0 = kt * BK;
        const uint32_t aBase = sAu + buf * A_STAGE * 2;
        const uint32_t bBase = sBu + buf * B_STAGE * 2;
#pragma unroll
        for (int t = 0; t < 4; t++) {
            int c = tid + t * 256;
            int row = c >> 3, ch = c & 7;
            cp_async_16(aBase + (row * LDA + ch * 8) * 2,
                        Ab + (size_t)row * K + k0 + ch * 8);
        }
#pragma unroll
        for (int t = 0; t < 4; t++) {
            int c = tid + t * 256;
            int row = c >> 4, ch = c & 15;
            cp_async_16(bBase + (row * LDB + ch * 8) * 2,
                        Bb + (size_t)(k0 + row) * N + ch * 8);
        }
        cp_commit();
    };

    float acc[4][4][4];
#pragma unroll
    for (int i = 0; i < 4; i++)
#pragma unroll
        for (int j = 0; j < 4; j++)
#pragma unroll
            for (int r = 0; r < 4; r++) acc[i][j][r] = 0.0f;

    issue(0, 0);
    if (totalStages > 1) issue(1, 1); else cp_commit();

    // ldmatrix lane geometry (validated R4-R7)
    const int q = lane >> 3, r8 = lane & 7;
    const int aRow = r8 + (q & 1) * 8;
    const int aK8 = (q >> 1) * 8;
    const int bRow = r8 + (q & 1) * 8;
    const int bC8 = (q >> 1) * 8;

    for (int ls = 0; ls < totalStages; ls++) {
        cp_wait<STAGES - 2>();
        __syncthreads();   // also guards reuse of the buffer prefetched below
        const int s = ls % STAGES;

        if (ls + 2 < totalStages) issue((ls + 2) % STAGES, ls + 2);
        else cp_commit();                        // uniform group accounting

        const uint32_t aSt = sAu + s * A_STAGE * 2;
        const uint32_t bSt = sBu + s * B_STAGE * 2;

        uint32_t rbb[2][4][2];
        auto loadB = [&](uint32_t (*rb)[2], int kk) {
#pragma unroll
            for (int p = 0; p < 2; p++) {
                uint32_t t4[4];
                ldsm_x4_t(t4, bSt + ((kk * 16 + bRow) * LDB + wn + p * 16 + bC8) * 2);
                rb[2 * p][0] = t4[0]; rb[2 * p][1] = t4[1];
                rb[2 * p + 1][0] = t4[2]; rb[2 * p + 1][1] = t4[3];
            }
        };
        loadB(rbb[0], 0);
#pragma unroll
        for (int kk = 0; kk < BK / 16; kk++) {
            uint32_t ra[4][4];
#pragma unroll
            for (int i = 0; i < 4; i++)
                ldsm_x4(ra[i], aSt + ((wm + i * 16 + aRow) * LDA + kk * 16 + aK8) * 2);
            if (kk < BK / 16 - 1) loadB(rbb[(kk + 1) & 1], kk + 1);
            uint32_t (*rb)[2] = rbb[kk & 1];
#pragma unroll
            for (int i = 0; i < 4; i++)
#pragma unroll
                for (int j = 0; j < 4; j++)
                    mma_16816(acc[i][j], ra[i], rb[j]);
        }

        // tile finished -> epilogue from registers (overlaps in-flight cp.async
        // for the next tile; no smem involved, so no extra sync needed)
        if ((ls & 63) == 63) {
            int bm, bn;
            tile_coords(bid + (ls >> 6) * NCTA, bm, bn);
            const int gId = lane >> 2, tI = lane & 3;
#pragma unroll
            for (int i = 0; i < 4; i++) {
                const int row0 = bm * BM + wm + i * 16 + gId;
#pragma unroll
                for (int j = 0; j < 4; j++) {
                    const int col = bn * BN + wn + j * 8 + tI * 2;
                    const float bx = bias[col], by = bias[col + 1];
                    float2 v0 = make_float2(acc[i][j][0] + bx, acc[i][j][1] + by);
                    float2 v1 = make_float2(acc[i][j][2] + bx, acc[i][j][3] + by);
                    *reinterpret_cast<float2*>(C + (size_t)row0 * N + col) = v0;
                    *reinterpret_cast<float2*>(C + (size_t)(row0 + 8) * N + col) = v1;
#pragma unroll
                    for (int r = 0; r < 4; r++) acc[i][j][r] = 0.0f;
                }
            }
        }
    }
}

// ---------------------------------------------------------------------------
// Launch
// ---------------------------------------------------------------------------
extern "C" void kernel_launch(void* const* d_in, const int* in_sizes, int n_in,
                              void* d_out, int out_size) {
    const float* x    = (const float*)d_in[0];   // [M, K]
    const float* w    = (const float*)d_in[1];   // [K, N]
    const float* bias = (const float*)d_in[2];   // [N]

    const int N = in_sizes[2];
    const int K = in_sizes[1] / N;
    const int M = in_sizes[0] / K;

    __half* gA = nullptr;
    __half* gB = nullptr;
    cudaGetSymbolAddress((void**)&gA, g_A);
    cudaGetSymbolAddress((void**)&gB, g_B);

    {   // quant+dequant x and W (both have contiguous 128-blocks)
        int quadsA = in_sizes[0] / 512;
        int quadsB = in_sizes[1] / 512;
        quant_kernel<<<(quadsA + 7) / 8, 256>>>(x, gA, quadsA);
        quant_kernel<<<(quadsB + 7) / 8, 256>>>(w, gB, quadsB);
    }
    {   // persistent GEMM + fused bias
        static bool attr_set = false;
        if (!attr_set) {
            cudaFuncSetAttribute(gemm_mma_persist,
                                 cudaFuncAttributeMaxDynamicSharedMemorySize,
                                 (int)SMEM_BYTES);
            attr_set = true;
        }
        const int nTiles = (M / BM) * (N / BN);  // 4096
        gemm_mma_persist<<<NCTA, 256, SMEM_BYTES>>>(gA, gB, bias, (float*)d_out,
                                                    M, N, K, nTiles);
    }
}

// round 9
// speedup vs baseline: 1.1043x; 1.1043x over previous
#include <cuda_runtime.h>
#include <cuda_fp16.h>
#include <cuda_fp8.h>
#include <cstdint>

#define DEV_INLINE __device__ __forceinline__

// ---------------------------------------------------------------------------
// Scratch (static device globals — allocation-free per harness rules)
// M=16384, K=4096, N=4096.
// ---------------------------------------------------------------------------
static __device__ __half g_A[(size_t)16384 * 4096];  // dequant x, fp16, [M,K]
static __device__ __half g_B[(size_t)4096 * 4096];   // dequant W, fp16, [K,N]

// ---------------------------------------------------------------------------
// Quantize + dequantize. One warp handles EIGHT 128-elem blocks (8 independent
// 16B-load streams -> MLP=8, interleaved shfl chains). Exact reference math:
// scale = max(amax/448, 1e-12); q = fp8_e4m3(v/scale); dq = float(q)*scale;
// one fp16 rounding at the end (only added approximation, ~2^-11 rel).
// ---------------------------------------------------------------------------
__global__ void quant_kernel(const float* __restrict__ in,
                             __half* __restrict__ out, int nocts) {
    const int oct = (blockIdx.x * blockDim.x + threadIdx.x) >> 5;
    const int lane = threadIdx.x & 31;
    if (oct >= nocts) return;
    const size_t base = (size_t)oct * 1024;

    float4 v[8];
#pragma unroll
    for (int b = 0; b < 8; b++)
        v[b] = reinterpret_cast<const float4*>(in + base + b * 128)[lane];

    float am[8];
#pragma unroll
    for (int b = 0; b < 8; b++)
        am[b] = fmaxf(fmaxf(fabsf(v[b].x), fabsf(v[b].y)),
                      fmaxf(fabsf(v[b].z), fabsf(v[b].w)));
#pragma unroll
    for (int o = 16; o > 0; o >>= 1) {
#pragma unroll
        for (int b = 0; b < 8; b++)
            am[b] = fmaxf(am[b], __shfl_xor_sync(0xFFFFFFFFu, am[b], o));
    }

#pragma unroll
    for (int b = 0; b < 8; b++) {
        const float s = fmaxf(__fdiv_rn(am[b], 448.0f), 1e-12f);
        float f[4] = {v[b].x, v[b].y, v[b].z, v[b].w};
        __half h[4];
#pragma unroll
        for (int i = 0; i < 4; i++) {
            __nv_fp8_storage_t q =
                __nv_cvt_float_to_fp8(__fdiv_rn(f[i], s), __NV_SATFINITE, __NV_E4M3);
            __half_raw hr = __nv_cvt_fp8_to_halfraw(q, __NV_E4M3);
            h[i] = __float2half_rn(__half2float(__half(hr)) * s);
        }
        reinterpret_cast<uint2*>(out + base + b * 128)[lane] =
            *reinterpret_cast<const uint2*>(h);
    }
}

// ---------------------------------------------------------------------------
// mma.sync GEMM (R7 proven config, reverted verbatim): C = A @ B + bias.
// CTA 128x128x64, 3-stage cp.async, 8 warps (2Mx4N), warp tile 64x32,
// 2 CTAs/SM, single __syncthreads per iter, B-fragment ping-pong prefetch.
// ---------------------------------------------------------------------------
static constexpr int BM = 128, BN = 128, BK = 64, STAGES = 3;
static constexpr int LDA = BK + 8;    // 72 halves = 144B (conflict-free ldsm)
static constexpr int LDB = BN + 8;    // 136 halves = 272B
static constexpr int A_STAGE = BM * LDA;
static constexpr int B_STAGE = BK * LDB;
static constexpr size_t SMEM_BYTES = (size_t)STAGES * (A_STAGE + B_STAGE) * 2;  // 107520

DEV_INLINE uint32_t smem_u32(const void* p) {
    return (uint32_t)__cvta_generic_to_shared(p);
}
DEV_INLINE void cp_async_16(uint32_t dst, const void* src) {
    asm volatile("cp.async.cg.shared.global [%0], [%1], 16;\n" :: "r"(dst), "l"(src));
}
DEV_INLINE void cp_commit() { asm volatile("cp.async.commit_group;\n"); }
template <int NN> DEV_INLINE void cp_wait() {
    asm volatile("cp.async.wait_group %0;\n" :: "n"(NN));
}
DEV_INLINE void ldsm_x4(uint32_t* r, uint32_t addr) {
    asm volatile("ldmatrix.sync.aligned.m8n8.x4.shared.b16 {%0,%1,%2,%3}, [%4];"
                 : "=r"(r[0]), "=r"(r[1]), "=r"(r[2]), "=r"(r[3]) : "r"(addr));
}
DEV_INLINE void ldsm_x4_t(uint32_t* r, uint32_t addr) {
    asm volatile("ldmatrix.sync.aligned.m8n8.x4.trans.shared.b16 {%0,%1,%2,%3}, [%4];"
                 : "=r"(r[0]), "=r"(r[1]), "=r"(r[2]), "=r"(r[3]) : "r"(addr));
}
DEV_INLINE void mma_16816(float* d, const uint32_t* a, const uint32_t* b) {
    asm volatile(
        "mma.sync.aligned.m16n8k16.row.col.f32.f16.f16.f32 "
        "{%0,%1,%2,%3}, {%4,%5,%6,%7}, {%8,%9}, {%0,%1,%2,%3};"
        : "+f"(d[0]), "+f"(d[1]), "+f"(d[2]), "+f"(d[3])
        : "r"(a[0]), "r"(a[1]), "r"(a[2]), "r"(a[3]), "r"(b[0]), "r"(b[1]));
}

__global__ void __launch_bounds__(256, 2)
gemm_mma_kernel(const __half* __restrict__ A, const __half* __restrict__ B,
                const float* __restrict__ bias, float* __restrict__ C,
                int M, int N, int K) {
    extern __shared__ __align__(128) __half smem[];
    __half* sA = smem;                          // [STAGES][BM][LDA]
    __half* sB = smem + STAGES * A_STAGE;       // [STAGES][BK][LDB]

    const int tid = threadIdx.x;
    const int lane = tid & 31;
    const int warp = tid >> 5;
    const int wm = (warp & 1) * 64;
    const int wn = (warp >> 1) * 32;

    // panel swizzle: 512-CTA panels (16 bm x 32 bn)
    const int linear = blockIdx.y * gridDim.x + blockIdx.x;  // grid=(32,128)
    const int bm = (linear >> 9) * 16 + (linear & 15);
    const int bn = (linear >> 4) & 31;

    const __half* Ab = A + (size_t)bm * BM * K;
    const __half* Bb = B + (size_t)bn * BN;

    const uint32_t sAu = smem_u32(sA);
    const uint32_t sBu = smem_u32(sB);

    auto issue = [&](int stage, int kt) {
        const int k0 = kt * BK;
        const uint32_t aBase = sAu + stage * A_STAGE * 2;
        const uint32_t bBase = sBu + stage * B_STAGE * 2;
#pragma unroll
        for (int t = 0; t < 4; t++) {
            int c = tid + t * 256;
            int row = c >> 3, ch = c & 7;
            cp_async_16(aBase + (row * LDA + ch * 8) * 2,
                        Ab + (size_t)row * K + k0 + ch * 8);
        }
#pragma unroll
        for (int t = 0; t < 4; t++) {
            int c = tid + t * 256;
            int row = c >> 4, ch = c & 15;
            cp_async_16(bBase + (row * LDB + ch * 8) * 2,
                        Bb + (size_t)(k0 + row) * N + ch * 8);
        }
        cp_commit();
    };

    float acc[4][4][4];
#pragma unroll
    for (int i = 0; i < 4; i++)
#pragma unroll
        for (int j = 0; j < 4; j++)
#pragma unroll
            for (int r = 0; r < 4; r++) acc[i][j][r] = 0.0f;

    const int KT = K / BK;
    issue(0, 0);
    issue(1, 1);

    // ldmatrix lane geometry (validated R4-R7)
    const int q = lane >> 3, r8 = lane & 7;
    const int aRow = r8 + (q & 1) * 8;
    const int aK8 = (q >> 1) * 8;
    const int bRow = r8 + (q & 1) * 8;
    const int bC8 = (q >> 1) * 8;

    for (int kt = 0; kt < KT; kt++) {
        cp_wait<STAGES - 2>();
        __syncthreads();   // also guards reuse of stage (kt-1)%3 prefetch target
        const int s = kt % STAGES;

        if (kt + 2 < KT) issue((kt + 2) % STAGES, kt + 2);
        else cp_commit();                        // uniform group accounting

        const uint32_t aSt = sAu + s * A_STAGE * 2;
        const uint32_t bSt = sBu + s * B_STAGE * 2;

        // B-fragment ping-pong: load B(kk+1) while MMAs consume B(kk)
        uint32_t rbb[2][4][2];
        auto loadB = [&](uint32_t (*rb)[2], int kk) {
#pragma unroll
            for (int p = 0; p < 2; p++) {
                uint32_t t4[4];
                ldsm_x4_t(t4, bSt + ((kk * 16 + bRow) * LDB + wn + p * 16 + bC8) * 2);
                rb[2 * p][0] = t4[0]; rb[2 * p][1] = t4[1];
                rb[2 * p + 1][0] = t4[2]; rb[2 * p + 1][1] = t4[3];
            }
        };
        loadB(rbb[0], 0);
#pragma unroll
        for (int kk = 0; kk < BK / 16; kk++) {
            uint32_t ra[4][4];
#pragma unroll
            for (int i = 0; i < 4; i++)
                ldsm_x4(ra[i], aSt + ((wm + i * 16 + aRow) * LDA + kk * 16 + aK8) * 2);
            if (kk < BK / 16 - 1) loadB(rbb[(kk + 1) & 1], kk + 1);
            uint32_t (*rb)[2] = rbb[kk & 1];
#pragma unroll
            for (int i = 0; i < 4; i++)
#pragma unroll
                for (int j = 0; j < 4; j++)
                    mma_16816(acc[i][j], ra[i], rb[j]);
        }
    }

    // epilogue: fused bias, direct stores
    const int gId = lane >> 2, tI = lane & 3;
#pragma unroll
    for (int i = 0; i < 4; i++) {
        const int row0 = bm * BM + wm + i * 16 + gId;
#pragma unroll
        for (int j = 0; j < 4; j++) {
            const int col = bn * BN + wn + j * 8 + tI * 2;
            const float bx = bias[col], by = bias[col + 1];
            float2 v0 = make_float2(acc[i][j][0] + bx, acc[i][j][1] + by);
            float2 v1 = make_float2(acc[i][j][2] + bx, acc[i][j][3] + by);
            *reinterpret_cast<float2*>(C + (size_t)row0 * N + col) = v0;
            *reinterpret_cast<float2*>(C + (size_t)(row0 + 8) * N + col) = v1;
        }
    }
}

// ---------------------------------------------------------------------------
// Launch
// ---------------------------------------------------------------------------
extern "C" void kernel_launch(void* const* d_in, const int* in_sizes, int n_in,
                              void* d_out, int out_size) {
    const float* x    = (const float*)d_in[0];   // [M, K]
    const float* w    = (const float*)d_in[1];   // [K, N]
    const float* bias = (const float*)d_in[2];   // [N]

    const int N = in_sizes[2];
    const int K = in_sizes[1] / N;
    const int M = in_sizes[0] / K;

    __half* gA = nullptr;
    __half* gB = nullptr;
    cudaGetSymbolAddress((void**)&gA, g_A);
    cudaGetSymbolAddress((void**)&gB, g_B);

    {   // quant+dequant x and W (both have contiguous 128-blocks)
        int octsA = in_sizes[0] / 1024;
        int octsB = in_sizes[1] / 1024;
        quant_kernel<<<(octsA + 7) / 8, 256>>>(x, gA, octsA);
        quant_kernel<<<(octsB + 7) / 8, 256>>>(w, gB, octsB);
    }
    {   // GEMM + fused bias (R7 config)
        static bool attr_set = false;
        if (!attr_set) {
            cudaFuncSetAttribute(gemm_mma_kernel,
                                 cudaFuncAttributeMaxDynamicSharedMemorySize,
                                 (int)SMEM_BYTES);
            attr_set = true;
        }
        dim3 grid(N / BN, M / BM);   // (32, 128) -> panel swizzle inside
        gemm_mma_kernel<<<grid, 256, SMEM_BYTES>>>(gA, gB, bias, (float*)d_out,
                                                   M, N, K);
    }
}

// round 10
// speedup vs baseline: 1.1090x; 1.0042x over previous
#include <cuda_runtime.h>
#include <cuda_fp16.h>
#include <cuda_fp8.h>
#include <cstdint>

#define DEV_INLINE __device__ __forceinline__

// ---------------------------------------------------------------------------
// Scratch (static device globals — allocation-free per harness rules)
// M=16384, K=4096, N=4096.
// ---------------------------------------------------------------------------
static __device__ __half g_A[(size_t)16384 * 4096];  // dequant x, fp16, [M,K]
static __device__ __half g_B[(size_t)4096 * 4096];   // dequant W, fp16, [K,N]

// ---------------------------------------------------------------------------
// Fused quantize + dequantize for BOTH tensors in one launch.
// Blocks [0, octsX) handle x; blocks [octsX, octsX+octsW) handle W.
// One warp = four 128-elem quant blocks (blocks contiguous for both tensors).
// Exact reference math: scale = max(amax/448, 1e-12); q = fp8_e4m3(v/scale);
// dq = float(q)*scale; one fp16 rounding at the end (only added approx).
// __ldcs: inputs are read exactly once -> evict-streaming, keep L2 for the
// fp16 scratch the GEMM re-reads.
// ---------------------------------------------------------------------------
__global__ void quant_both_kernel(const float* __restrict__ x,
                                  const float* __restrict__ w,
                                  __half* __restrict__ outX,
                                  __half* __restrict__ outW,
                                  int quadsX, int quadsTotal) {
    const int quad = (blockIdx.x * blockDim.x + threadIdx.x) >> 5;
    const int lane = threadIdx.x & 31;
    if (quad >= quadsTotal) return;

    const float* in;
    __half* out;
    size_t base;
    if (quad < quadsX) {
        in = x; out = outX; base = (size_t)quad * 512;
    } else {
        in = w; out = outW; base = (size_t)(quad - quadsX) * 512;
    }

    float4 v[4];
#pragma unroll
    for (int b = 0; b < 4; b++)
        v[b] = __ldcs(reinterpret_cast<const float4*>(in + base + b * 128) + lane);

    float am[4];
#pragma unroll
    for (int b = 0; b < 4; b++)
        am[b] = fmaxf(fmaxf(fabsf(v[b].x), fabsf(v[b].y)),
                      fmaxf(fabsf(v[b].z), fabsf(v[b].w)));
#pragma unroll
    for (int o = 16; o > 0; o >>= 1) {
#pragma unroll
        for (int b = 0; b < 4; b++)
            am[b] = fmaxf(am[b], __shfl_xor_sync(0xFFFFFFFFu, am[b], o));
    }

#pragma unroll
    for (int b = 0; b < 4; b++) {
        const float s = fmaxf(__fdiv_rn(am[b], 448.0f), 1e-12f);
        float f[4] = {v[b].x, v[b].y, v[b].z, v[b].w};
        __half h[4];
#pragma unroll
        for (int i = 0; i < 4; i++) {
            __nv_fp8_storage_t q =
                __nv_cvt_float_to_fp8(__fdiv_rn(f[i], s), __NV_SATFINITE, __NV_E4M3);
            __half_raw hr = __nv_cvt_fp8_to_halfraw(q, __NV_E4M3);
            h[i] = __float2half_rn(__half2float(__half(hr)) * s);
        }
        reinterpret_cast<uint2*>(out + base + b * 128)[lane] =
            *reinterpret_cast<const uint2*>(h);
    }
}

// ---------------------------------------------------------------------------
// mma.sync GEMM (R7 proven config, bit-identical mainloop): C = A @ B + bias.
// CTA 128x128x64, 3-stage cp.async, 8 warps (2Mx4N), warp tile 64x32,
// 2 CTAs/SM, single __syncthreads per iter, B-fragment ping-pong prefetch.
// ---------------------------------------------------------------------------
static constexpr int BM = 128, BN = 128, BK = 64, STAGES = 3;
static constexpr int LDA = BK + 8;    // 72 halves = 144B (conflict-free ldsm)
static constexpr int LDB = BN + 8;    // 136 halves = 272B
static constexpr int A_STAGE = BM * LDA;
static constexpr int B_STAGE = BK * LDB;
static constexpr size_t SMEM_BYTES = (size_t)STAGES * (A_STAGE + B_STAGE) * 2;  // 107520

DEV_INLINE uint32_t smem_u32(const void* p) {
    return (uint32_t)__cvta_generic_to_shared(p);
}
DEV_INLINE void cp_async_16(uint32_t dst, const void* src) {
    asm volatile("cp.async.cg.shared.global [%0], [%1], 16;\n" :: "r"(dst), "l"(src));
}
DEV_INLINE void cp_commit() { asm volatile("cp.async.commit_group;\n"); }
template <int NN> DEV_INLINE void cp_wait() {
    asm volatile("cp.async.wait_group %0;\n" :: "n"(NN));
}
DEV_INLINE void ldsm_x4(uint32_t* r, uint32_t addr) {
    asm volatile("ldmatrix.sync.aligned.m8n8.x4.shared.b16 {%0,%1,%2,%3}, [%4];"
                 : "=r"(r[0]), "=r"(r[1]), "=r"(r[2]), "=r"(r[3]) : "r"(addr));
}
DEV_INLINE void ldsm_x4_t(uint32_t* r, uint32_t addr) {
    asm volatile("ldmatrix.sync.aligned.m8n8.x4.trans.shared.b16 {%0,%1,%2,%3}, [%4];"
                 : "=r"(r[0]), "=r"(r[1]), "=r"(r[2]), "=r"(r[3]) : "r"(addr));
}
DEV_INLINE void mma_16816(float* d, const uint32_t* a, const uint32_t* b) {
    asm volatile(
        "mma.sync.aligned.m16n8k16.row.col.f32.f16.f16.f32 "
        "{%0,%1,%2,%3}, {%4,%5,%6,%7}, {%8,%9}, {%0,%1,%2,%3};"
        : "+f"(d[0]), "+f"(d[1]), "+f"(d[2]), "+f"(d[3])
        : "r"(a[0]), "r"(a[1]), "r"(a[2]), "r"(a[3]), "r"(b[0]), "r"(b[1]));
}

__global__ void __launch_bounds__(256, 2)
gemm_mma_kernel(const __half* __restrict__ A, const __half* __restrict__ B,
                const float* __restrict__ bias, float* __restrict__ C,
                int M, int N, int K) {
    extern __shared__ __align__(128) __half smem[];
    __half* sA = smem;                          // [STAGES][BM][LDA]
    __half* sB = smem + STAGES * A_STAGE;       // [STAGES][BK][LDB]

    const int tid = threadIdx.x;
    const int lane = tid & 31;
    const int warp = tid >> 5;
    const int wm = (warp & 1) * 64;
    const int wn = (warp >> 1) * 32;

    // panel swizzle: 512-CTA panels (16 bm x 32 bn)
    const int linear = blockIdx.y * gridDim.x + blockIdx.x;  // grid=(32,128)
    const int bm = (linear >> 9) * 16 + (linear & 15);
    const int bn = (linear >> 4) & 31;

    const __half* Ab = A + (size_t)bm * BM * K;
    const __half* Bb = B + (size_t)bn * BN;

    const uint32_t sAu = smem_u32(sA);
    const uint32_t sBu = smem_u32(sB);

    auto issue = [&](int stage, int kt) {
        const int k0 = kt * BK;
        const uint32_t aBase = sAu + stage * A_STAGE * 2;
        const uint32_t bBase = sBu + stage * B_STAGE * 2;
#pragma unroll
        for (int t = 0; t < 4; t++) {
            int c = tid + t * 256;
            int row = c >> 3, ch = c & 7;
            cp_async_16(aBase + (row * LDA + ch * 8) * 2,
                        Ab + (size_t)row * K + k0 + ch * 8);
        }
#pragma unroll
        for (int t = 0; t < 4; t++) {
            int c = tid + t * 256;
            int row = c >> 4, ch = c & 15;
            cp_async_16(bBase + (row * LDB + ch * 8) * 2,
                        Bb + (size_t)(k0 + row) * N + ch * 8);
        }
        cp_commit();
    };

    float acc[4][4][4];
#pragma unroll
    for (int i = 0; i < 4; i++)
#pragma unroll
        for (int j = 0; j < 4; j++)
#pragma unroll
            for (int r = 0; r < 4; r++) acc[i][j][r] = 0.0f;

    const int KT = K / BK;
    issue(0, 0);
    issue(1, 1);

    // ldmatrix lane geometry (validated R4-R9)
    const int q = lane >> 3, r8 = lane & 7;
    const int aRow = r8 + (q & 1) * 8;
    const int aK8 = (q >> 1) * 8;
    const int bRow = r8 + (q & 1) * 8;
    const int bC8 = (q >> 1) * 8;

    for (int kt = 0; kt < KT; kt++) {
        cp_wait<STAGES - 2>();
        __syncthreads();   // also guards reuse of stage (kt-1)%3 prefetch target
        const int s = kt % STAGES;

        if (kt + 2 < KT) issue((kt + 2) % STAGES, kt + 2);
        else cp_commit();                        // uniform group accounting

        const uint32_t aSt = sAu + s * A_STAGE * 2;
        const uint32_t bSt = sBu + s * B_STAGE * 2;

        // B-fragment ping-pong: load B(kk+1) while MMAs consume B(kk)
        uint32_t rbb[2][4][2];
        auto loadB = [&](uint32_t (*rb)[2], int kk) {
#pragma unroll
            for (int p = 0; p < 2; p++) {
                uint32_t t4[4];
                ldsm_x4_t(t4, bSt + ((kk * 16 + bRow) * LDB + wn + p * 16 + bC8) * 2);
                rb[2 * p][0] = t4[0]; rb[2 * p][1] = t4[1];
                rb[2 * p + 1][0] = t4[2]; rb[2 * p + 1][1] = t4[3];
            }
        };
        loadB(rbb[0], 0);
#pragma unroll
        for (int kk = 0; kk < BK / 16; kk++) {
            uint32_t ra[4][4];
#pragma unroll
            for (int i = 0; i < 4; i++)
                ldsm_x4(ra[i], aSt + ((wm + i * 16 + aRow) * LDA + kk * 16 + aK8) * 2);
            if (kk < BK / 16 - 1) loadB(rbb[(kk + 1) & 1], kk + 1);
            uint32_t (*rb)[2] = rbb[kk & 1];
#pragma unroll
            for (int i = 0; i < 4; i++)
#pragma unroll
                for (int j = 0; j < 4; j++)
                    mma_16816(acc[i][j], ra[i], rb[j]);
        }
    }

    // epilogue: fused bias, direct stores
    const int gId = lane >> 2, tI = lane & 3;
#pragma unroll
    for (int i = 0; i < 4; i++) {
        const int row0 = bm * BM + wm + i * 16 + gId;
#pragma unroll
        for (int j = 0; j < 4; j++) {
            const int col = bn * BN + wn + j * 8 + tI * 2;
            const float bx = bias[col], by = bias[col + 1];
            float2 v0 = make_float2(acc[i][j][0] + bx, acc[i][j][1] + by);
            float2 v1 = make_float2(acc[i][j][2] + bx, acc[i][j][3] + by);
            *reinterpret_cast<float2*>(C + (size_t)row0 * N + col) = v0;
            *reinterpret_cast<float2*>(C + (size_t)(row0 + 8) * N + col) = v1;
        }
    }
}

// ---------------------------------------------------------------------------
// Launch
// ---------------------------------------------------------------------------
extern "C" void kernel_launch(void* const* d_in, const int* in_sizes, int n_in,
                              void* d_out, int out_size) {
    const float* x    = (const float*)d_in[0];   // [M, K]
    const float* w    = (const float*)d_in[1];   // [K, N]
    const float* bias = (const float*)d_in[2];   // [N]

    const int N = in_sizes[2];
    const int K = in_sizes[1] / N;
    const int M = in_sizes[0] / K;

    __half* gA = nullptr;
    __half* gB = nullptr;
    cudaGetSymbolAddress((void**)&gA, g_A);
    cudaGetSymbolAddress((void**)&gB, g_B);

    {   // single fused quant+dequant launch for x AND W
        int quadsX = in_sizes[0] / 512;
        int quadsW = in_sizes[1] / 512;
        int quadsTotal = quadsX + quadsW;
        quant_both_kernel<<<(quadsTotal + 7) / 8, 256>>>(x, w, gA, gB,
                                                         quadsX, quadsTotal);
    }
    {   // GEMM + fused bias (R7 config)
        static bool attr_set = false;
        if (!attr_set) {
            cudaFuncSetAttribute(gemm_mma_kernel,
                                 cudaFuncAttributeMaxDynamicSharedMemorySize,
                                 (int)SMEM_BYTES);
            attr_set = true;
        }
        dim3 grid(N / BN, M / BM);   // (32, 128) -> panel swizzle inside
        gemm_mma_kernel<<<grid, 256, SMEM_BYTES>>>(gA, gB, bias, (float*)d_out,
                                                   M, N, K);
    }
}